// round 6
// baseline (speedup 1.0000x reference)
#include <cuda_runtime.h>
#include <cuda_bf16.h>
#include <math.h>
#include <stdint.h>

#define N_NODES  50000
#define N_EDGES  800000
#define FEAT     90
#define H        128
#define STEPS    4
#define N_GRAPHS 100
#define M_PAD    50048   // 128 * 391
#define M_TILES  (M_PAD / 128)
#define NOUT     384

typedef unsigned long long u64;

// ---------------- device scratch ----------------
__device__ float g_h  [(size_t)M_PAD * H];
__device__ float g_gx [(size_t)M_PAD * 3 * H];
__device__ float g_gh [(size_t)M_PAD * 3 * H];   // only r,z slices used
__device__ float g_pool[N_GRAPHS * H];
__device__ float g_cnt [N_GRAPHS];

// CSR for gather aggregation
__device__ int g_deg[N_NODES];
__device__ int g_off[N_NODES + 1];
__device__ int g_cur[N_NODES];
__device__ int g_eid[N_EDGES];

// bf16-split, transposed weights, layout [n][k]
__device__ __nv_bfloat16 g_wcomb_h[STEPS * 3 * H * H];  // W_msg[s] @ W_ih
__device__ __nv_bfloat16 g_wcomb_l[STEPS * 3 * H * H];
__device__ __nv_bfloat16 g_whh_h[3 * H * H];
__device__ __nv_bfloat16 g_whh_l[3 * H * H];

// ---------------- PTX helpers ----------------
__device__ __forceinline__ uint32_t smem_u32(const void* p) {
    uint32_t a;
    asm("{ .reg .u64 t; cvta.to.shared.u64 t, %1; cvt.u32.u64 %0, t; }" : "=r"(a) : "l"(p));
    return a;
}

__device__ __forceinline__ void ldsm_x4(uint32_t& r0, uint32_t& r1, uint32_t& r2, uint32_t& r3,
                                        uint32_t addr) {
    asm volatile("ldmatrix.sync.aligned.m8n8.x4.shared.b16 {%0,%1,%2,%3}, [%4];"
                 : "=r"(r0), "=r"(r1), "=r"(r2), "=r"(r3) : "r"(addr));
}

__device__ __forceinline__ void mma_bf16(float* c, const uint32_t* a, const uint32_t* b) {
    asm volatile(
        "mma.sync.aligned.m16n8k16.row.col.f32.bf16.bf16.f32 "
        "{%0,%1,%2,%3}, {%4,%5,%6,%7}, {%8,%9}, {%0,%1,%2,%3};"
        : "+f"(c[0]), "+f"(c[1]), "+f"(c[2]), "+f"(c[3])
        : "r"(a[0]), "r"(a[1]), "r"(a[2]), "r"(a[3]), "r"(b[0]), "r"(b[1]));
}

// swizzled tile offset: row r (0..127), 16B-chunk c (0..15); 256B rows
__device__ __forceinline__ uint32_t swz(int r, int c) {
    return (uint32_t)r * 256 + (uint32_t)((c ^ (r & 7)) << 4);
}

__device__ __forceinline__ float sigmoidf_(float x) { return 1.f / (1.f + expf(-x)); }

__device__ __forceinline__ uint32_t pack_bf16x2(float a, float b) {
    __nv_bfloat16 ha = __float2bfloat16(a);
    __nv_bfloat16 hb = __float2bfloat16(b);
    return (uint32_t)__bfloat16_as_ushort(ha) | ((uint32_t)__bfloat16_as_ushort(hb) << 16);
}

// ---------------- CSR build ----------------
__global__ void hist_kernel(const int* __restrict__ ei) {
    int e = blockIdx.x * 256 + threadIdx.x;
    if (e < N_EDGES) atomicAdd(&g_deg[ei[N_EDGES + e]], 1);
}

__global__ void scan_kernel() {   // single block, 1024 threads
    const int tid = threadIdx.x, lane = tid & 31, w = tid >> 5;
    __shared__ int wsum[32];
    int total = 0;
    for (int base = 0; base < N_NODES; base += 1024) {
        int i = base + tid;
        int v = (i < N_NODES) ? g_deg[i] : 0;
        int x = v;
        #pragma unroll
        for (int d = 1; d < 32; d <<= 1) {
            int t = __shfl_up_sync(0xFFFFFFFFu, x, d);
            if (lane >= d) x += t;
        }
        if (lane == 31) wsum[w] = x;
        __syncthreads();
        if (w == 0) {
            int y = wsum[lane];
            #pragma unroll
            for (int d = 1; d < 32; d <<= 1) {
                int t = __shfl_up_sync(0xFFFFFFFFu, y, d);
                if (lane >= d) y += t;
            }
            wsum[lane] = y;
        }
        __syncthreads();
        int woff = (w == 0) ? 0 : wsum[w - 1];
        int excl = total + woff + x - v;
        if (i < N_NODES) { g_off[i] = excl; g_cur[i] = excl; }
        int chunk = wsum[31];
        __syncthreads();
        total += chunk;
    }
    if (tid == 0) g_off[N_NODES] = total;
}

__global__ void fill_kernel(const int* __restrict__ ei) {
    int e = blockIdx.x * 256 + threadIdx.x;
    if (e < N_EDGES) {
        int dst = ei[N_EDGES + e];
        int pos = atomicAdd(&g_cur[dst], 1);
        g_eid[pos] = ei[e];
    }
}

// ---------------- weight prep ----------------
__global__ void prep_whh(const float* __restrict__ Whh) {
    int j = blockIdx.x * 256 + threadIdx.x;
    if (j >= 3 * H * H) return;
    int n = j >> 7, k = j & 127;
    float v = Whh[k * 384 + n];
    __nv_bfloat16 hi = __float2bfloat16(v);
    __nv_bfloat16 lo = __float2bfloat16(v - __bfloat162float(hi));
    g_whh_h[j] = hi; g_whh_l[j] = lo;
}

__global__ void prep_wcomb(const float* __restrict__ Wmsg,
                           const float* __restrict__ Wih) {
    int i = blockIdx.x * 256 + threadIdx.x;
    if (i >= STEPS * 3 * H * H) return;
    int s = i / (3 * H * H);
    int r = i % (3 * H * H);
    int k = r / 384;
    int n = r % 384;
    const float* wm = Wmsg + (s << 14) + k * H;
    float acc = 0.f;
    #pragma unroll 8
    for (int j = 0; j < H; j++) acc = fmaf(wm[j], Wih[j * 384 + n], acc);
    __nv_bfloat16 hi = __float2bfloat16(acc);
    __nv_bfloat16 lo = __float2bfloat16(acc - __bfloat162float(hi));
    size_t o = (size_t)s * 3 * H * H + (size_t)n * H + k;
    g_wcomb_h[o] = hi; g_wcomb_l[o] = lo;
}

// ---------------- fused GEMM ---------------------------------------------------
// MODE 0 (gx): A = CSR-gather of g_h rows (agg), C = g_gx, bias = b_ih.
// MODE 1 (gh): A = g_h rows; n-tiles 0,1 -> g_gh (+b_hh); n-tile 2 -> fused GRU,
//              reads g_gx/g_gh/g_h, writes g_h.
// bf16x3: C = Ah*Bh + Ah*Bl + Al*Bh (fp32 accum). 512 thr, warp tile m32 x n32.
#define SM_A_H 0
#define SM_A_L 32768
#define SM_B_H 65536
#define SM_B_L 98304
#define SM_BIAS 131072
#define GEMM_SMEM (131072 + 1536)

template<int MODE>
__global__ void __launch_bounds__(512, 1) gemm_fused(
        const __nv_bfloat16* __restrict__ Bh, const __nv_bfloat16* __restrict__ Bl,
        const float* __restrict__ bias) {
    extern __shared__ char smem[];
    const uint32_t sbase = smem_u32(smem);
    const int tid = threadIdx.x;
    const int wid = tid >> 5;
    const int lane = tid & 31;
    const int m0 = blockIdx.x * 128;

    // ---- build A tile (128x128), bf16 hi/lo split, swizzled ----
    if (MODE == 0) {
        // CSR gather: warp w handles rows w*8 .. w*8+7
        #pragma unroll
        for (int i = 0; i < 8; i++) {
            const int row = wid * 8 + i;
            const int node = m0 + row;
            float4 acc = make_float4(0.f, 0.f, 0.f, 0.f);
            if (node < N_NODES) {
                const int beg = g_off[node], end = g_off[node + 1];
                #pragma unroll 4
                for (int e = beg; e < end; e++) {
                    int src = __ldg(&g_eid[e]);
                    float4 v = *(const float4*)(g_h + (size_t)src * H + lane * 4);
                    acc.x += v.x; acc.y += v.y; acc.z += v.z; acc.w += v.w;
                }
            }
            __nv_bfloat16 h0 = __float2bfloat16(acc.x);
            __nv_bfloat16 h1 = __float2bfloat16(acc.y);
            __nv_bfloat16 h2 = __float2bfloat16(acc.z);
            __nv_bfloat16 h3 = __float2bfloat16(acc.w);
            uint2 hw, lw;
            hw.x = (uint32_t)__bfloat16_as_ushort(h0) | ((uint32_t)__bfloat16_as_ushort(h1) << 16);
            hw.y = (uint32_t)__bfloat16_as_ushort(h2) | ((uint32_t)__bfloat16_as_ushort(h3) << 16);
            lw.x = pack_bf16x2(acc.x - __bfloat162float(h0), acc.y - __bfloat162float(h1));
            lw.y = pack_bf16x2(acc.z - __bfloat162float(h2), acc.w - __bfloat162float(h3));
            uint32_t off = swz(row, lane >> 1) + (lane & 1) * 8;
            *(uint2*)(smem + SM_A_H + off) = hw;
            *(uint2*)(smem + SM_A_L + off) = lw;
        }
    } else {
        const float* Ab = g_h + (size_t)m0 * 128;
        #pragma unroll
        for (int it = 0; it < 8; it++) {
            int idx = it * 512 + tid;          // 0..4095
            int row = idx >> 5;
            int q = idx & 31;                  // float4 index; k0 = q*4
            float4 v = *(const float4*)(Ab + row * 128 + q * 4);
            __nv_bfloat16 h0 = __float2bfloat16(v.x);
            __nv_bfloat16 h1 = __float2bfloat16(v.y);
            __nv_bfloat16 h2 = __float2bfloat16(v.z);
            __nv_bfloat16 h3 = __float2bfloat16(v.w);
            uint2 hw, lw;
            hw.x = (uint32_t)__bfloat16_as_ushort(h0) | ((uint32_t)__bfloat16_as_ushort(h1) << 16);
            hw.y = (uint32_t)__bfloat16_as_ushort(h2) | ((uint32_t)__bfloat16_as_ushort(h3) << 16);
            lw.x = pack_bf16x2(v.x - __bfloat162float(h0), v.y - __bfloat162float(h1));
            lw.y = pack_bf16x2(v.z - __bfloat162float(h2), v.w - __bfloat162float(h3));
            uint32_t off = swz(row, q >> 1) + (q & 1) * 8;
            *(uint2*)(smem + SM_A_H + off) = hw;
            *(uint2*)(smem + SM_A_L + off) = lw;
        }
    }
    // ---- bias -> smem ----
    for (int i = tid; i < NOUT; i += 512)
        *(float*)(smem + SM_BIAS + i * 4) = bias[i];

    const int wm = (wid & 3) * 32;
    const int wn = (wid >> 2) * 32;

    #pragma unroll
    for (int nt = 0; nt < 3; nt++) {
        __syncthreads();
        // ---- load B sub-tile 128n x 128k hi+lo, swizzled ----
        {
            const __nv_bfloat16* bh = Bh + (size_t)nt * 128 * 128;
            const __nv_bfloat16* bl = Bl + (size_t)nt * 128 * 128;
            #pragma unroll
            for (int it = 0; it < 4; it++) {
                int idx = it * 512 + tid;
                int row = idx >> 4;
                int c = idx & 15;
                uint32_t off = swz(row, c);
                *(uint4*)(smem + SM_B_H + off) = *(const uint4*)(bh + row * 128 + c * 8);
                *(uint4*)(smem + SM_B_L + off) = *(const uint4*)(bl + row * 128 + c * 8);
            }
        }
        __syncthreads();

        // ---- compute ----
        float acc[2][4][4];
        #pragma unroll
        for (int mi = 0; mi < 2; mi++)
            #pragma unroll
            for (int ni = 0; ni < 4; ni++)
                #pragma unroll
                for (int j = 0; j < 4; j++) acc[mi][ni][j] = 0.f;

        #pragma unroll
        for (int ks = 0; ks < 8; ks++) {
            const int c0 = ks * 2;
            uint32_t ah[2][4], al[2][4], bh[4][2], bl[4][2];
            {
                int arow = (lane & 15);
                int ac = c0 + (lane >> 4);
                #pragma unroll
                for (int mi = 0; mi < 2; mi++) {
                    uint32_t o = swz(wm + mi * 16 + arow, ac);
                    ldsm_x4(ah[mi][0], ah[mi][1], ah[mi][2], ah[mi][3], sbase + SM_A_H + o);
                    ldsm_x4(al[mi][0], al[mi][1], al[mi][2], al[mi][3], sbase + SM_A_L + o);
                }
            }
            {
                int brow = ((lane >> 4) << 3) + (lane & 7);
                int bc = c0 + ((lane >> 3) & 1);
                #pragma unroll
                for (int nj = 0; nj < 2; nj++) {
                    uint32_t o = swz(wn + nj * 16 + brow, bc);
                    uint32_t t0, t1, t2, t3;
                    ldsm_x4(t0, t1, t2, t3, sbase + SM_B_H + o);
                    bh[nj * 2][0] = t0; bh[nj * 2][1] = t1;
                    bh[nj * 2 + 1][0] = t2; bh[nj * 2 + 1][1] = t3;
                    ldsm_x4(t0, t1, t2, t3, sbase + SM_B_L + o);
                    bl[nj * 2][0] = t0; bl[nj * 2][1] = t1;
                    bl[nj * 2 + 1][0] = t2; bl[nj * 2 + 1][1] = t3;
                }
            }
            #pragma unroll
            for (int mi = 0; mi < 2; mi++)
                #pragma unroll
                for (int ni = 0; ni < 4; ni++) {
                    mma_bf16(acc[mi][ni], ah[mi], bh[ni]);
                    mma_bf16(acc[mi][ni], ah[mi], bl[ni]);
                    mma_bf16(acc[mi][ni], al[mi], bh[ni]);
                }
        }

        // ---- epilogue ----
        const int r0 = m0 + wm + (lane >> 2);
        const int cl = wn + (lane & 3) * 2;          // col within 128-tile
        if (MODE == 1 && nt == 2) {
            // fused GRU: acc = h @ Whh_n (pre-bias); combine with gx, gh_r/z, h
            #pragma unroll
            for (int mi = 0; mi < 2; mi++) {
                #pragma unroll
                for (int ni = 0; ni < 4; ni++) {
                    const int c = cl + ni * 8;
                    float2 bb = *(const float2*)(smem + SM_BIAS + (256 + c) * 4);
                    #pragma unroll
                    for (int rr = 0; rr < 2; rr++) {
                        const int row = r0 + mi * 16 + rr * 8;
                        const size_t gxo = (size_t)row * 384 + c;
                        float2 xr = *(const float2*)(g_gx + gxo);
                        float2 xz = *(const float2*)(g_gx + gxo + 128);
                        float2 xn = *(const float2*)(g_gx + gxo + 256);
                        float2 hr = *(const float2*)(g_gh + gxo);
                        float2 hz = *(const float2*)(g_gh + gxo + 128);
                        float2 hv = *(const float2*)(g_h + (size_t)row * 128 + c);
                        float hn0 = acc[mi][ni][rr * 2]     + bb.x;
                        float hn1 = acc[mi][ni][rr * 2 + 1] + bb.y;
                        float r0_ = sigmoidf_(xr.x + hr.x);
                        float r1_ = sigmoidf_(xr.y + hr.y);
                        float z0_ = sigmoidf_(xz.x + hz.x);
                        float z1_ = sigmoidf_(xz.y + hz.y);
                        float n0_ = tanhf(xn.x + r0_ * hn0);
                        float n1_ = tanhf(xn.y + r1_ * hn1);
                        float2 o;
                        o.x = (1.f - z0_) * n0_ + z0_ * hv.x;
                        o.y = (1.f - z1_) * n1_ + z1_ * hv.y;
                        *(float2*)(g_h + (size_t)row * 128 + c) = o;
                    }
                }
            }
        } else {
            float* C = (MODE == 0) ? g_gx : g_gh;
            #pragma unroll
            for (int mi = 0; mi < 2; mi++) {
                #pragma unroll
                for (int ni = 0; ni < 4; ni++) {
                    int col = nt * 128 + cl + ni * 8;
                    float2 bb = *(const float2*)(smem + SM_BIAS + col * 4);
                    float* c0p = C + (size_t)(r0 + mi * 16) * 384 + col;
                    float* c1p = C + (size_t)(r0 + mi * 16 + 8) * 384 + col;
                    *(float2*)c0p = make_float2(acc[mi][ni][0] + bb.x, acc[mi][ni][1] + bb.y);
                    *(float2*)c1p = make_float2(acc[mi][ni][2] + bb.x, acc[mi][ni][3] + bb.y);
                }
            }
        }
    }
}

// ---------------- embedding: h = relu(x @ W_emb), K=90 ----------------
__global__ void embed_kernel(const float* __restrict__ x,
                             const float* __restrict__ Wemb) {
    extern __shared__ float sm[];
    float* Ws = sm;               // FEAT*H
    float* xs = sm + FEAT * H;    // 32*FEAT
    const int tid = threadIdx.x;
    for (int i = tid; i < FEAT * H; i += 128) Ws[i] = Wemb[i];
    const int n0 = blockIdx.x * 32;
    for (int i = tid; i < 32 * FEAT; i += 128) {
        int r = i / FEAT, cc = i - r * FEAT;
        int n = n0 + r;
        xs[i] = (n < N_NODES) ? x[(size_t)n * FEAT + cc] : 0.f;
    }
    __syncthreads();
    const int c = tid;
    for (int r = 0; r < 32; r++) {
        float acc = 0.f;
        const float* xr = xs + r * FEAT;
        #pragma unroll 6
        for (int k = 0; k < FEAT; k++) acc = fmaf(xr[k], Ws[k * H + c], acc);
        g_h[(size_t)(n0 + r) * H + c] = fmaxf(acc, 0.f);
    }
}

// ---------------- pooling: sum relu(h) per graph (batch sorted) --------------
__global__ void pool_kernel(const int* __restrict__ batch) {
    __shared__ int bs[256];
    const int tid = threadIdx.x;        // 128 threads, one column each
    const int n0 = blockIdx.x * 256;
    const int cnt = min(256, N_NODES - n0);
    for (int i = tid; i < cnt; i += 128) bs[i] = batch[n0 + i];
    __syncthreads();
    const int c = tid;
    float sum = 0.f;
    int cur = bs[0];
    int run = 0;
    for (int i = 0; i < cnt; i++) {
        int b = bs[i];
        if (b != cur) {
            atomicAdd(&g_pool[cur * H + c], sum);
            if (c == 0) atomicAdd(&g_cnt[cur], (float)run);
            sum = 0.f; run = 0; cur = b;
        }
        sum += fmaxf(g_h[(size_t)(n0 + i) * H + c], 0.f);
        run++;
    }
    atomicAdd(&g_pool[cur * H + c], sum);
    if (c == 0) atomicAdd(&g_cnt[cur], (float)run);
}

// ---------------- head: mean -> Linear+ReLU -> Linear -> softplus ------------
__global__ void head_kernel(const float* __restrict__ W1, const float* __restrict__ b1,
                            const float* __restrict__ W2, const float* __restrict__ b2,
                            float* __restrict__ out) {
    __shared__ float ps[H];
    __shared__ float hs[H];
    const int g = blockIdx.x, c = threadIdx.x;
    float cnt = fmaxf(g_cnt[g], 1.f);
    ps[c] = g_pool[g * H + c] / cnt;
    __syncthreads();
    float acc = b1[c];
    #pragma unroll 8
    for (int k = 0; k < H; k++) acc = fmaf(ps[k], W1[k * H + c], acc);
    hs[c] = fmaxf(acc, 0.f) * W2[c];
    __syncthreads();
    for (int s = 64; s > 0; s >>= 1) {
        if (c < s) hs[c] += hs[c + s];
        __syncthreads();
    }
    if (c == 0) {
        float xv = hs[0] + b2[0];
        out[g] = (xv > 0.f) ? (xv + log1pf(expf(-xv))) : log1pf(expf(xv));
    }
}

// ---------------- launch ------------------------------------------------------
extern "C" void kernel_launch(void* const* d_in, const int* in_sizes, int n_in,
                              void* d_out, int out_size) {
    const float* x     = (const float*)d_in[0];
    const int*   ei    = (const int*)d_in[1];
    const int*   batch = (const int*)d_in[2];
    const float* W_emb = (const float*)d_in[3];
    const float* W_msg = (const float*)d_in[4];
    const float* W_ih  = (const float*)d_in[5];
    const float* W_hh  = (const float*)d_in[6];
    const float* b_ih  = (const float*)d_in[7];
    const float* b_hh  = (const float*)d_in[8];
    const float* W1    = (const float*)d_in[9];
    const float* b1    = (const float*)d_in[10];
    const float* W2    = (const float*)d_in[11];
    const float* b2    = (const float*)d_in[12];
    float* out = (float*)d_out;

    float *pool_p, *cnt_p;
    int* deg_p;
    cudaGetSymbolAddress((void**)&pool_p, g_pool);
    cudaGetSymbolAddress((void**)&cnt_p,  g_cnt);
    cudaGetSymbolAddress((void**)&deg_p,  g_deg);

    __nv_bfloat16 *wcomb_h, *wcomb_l, *whh_h, *whh_l;
    cudaGetSymbolAddress((void**)&wcomb_h, g_wcomb_h);
    cudaGetSymbolAddress((void**)&wcomb_l, g_wcomb_l);
    cudaGetSymbolAddress((void**)&whh_h,   g_whh_h);
    cudaGetSymbolAddress((void**)&whh_l,   g_whh_l);

    const int embed_smem = (FEAT * H + 32 * FEAT) * 4;  // 57600 B
    cudaFuncSetAttribute(embed_kernel,
                         cudaFuncAttributeMaxDynamicSharedMemorySize, embed_smem);
    cudaFuncSetAttribute(gemm_fused<0>,
                         cudaFuncAttributeMaxDynamicSharedMemorySize, GEMM_SMEM);
    cudaFuncSetAttribute(gemm_fused<1>,
                         cudaFuncAttributeMaxDynamicSharedMemorySize, GEMM_SMEM);

    // 0) CSR build + weight prep
    cudaMemsetAsync(deg_p, 0, N_NODES * sizeof(int));
    hist_kernel<<<(N_EDGES + 255) / 256, 256>>>(ei);
    scan_kernel<<<1, 1024>>>();
    fill_kernel<<<(N_EDGES + 255) / 256, 256>>>(ei);
    prep_whh<<<(3 * H * H + 255) / 256, 256>>>(W_hh);
    prep_wcomb<<<(STEPS * 3 * H * H + 255) / 256, 256>>>(W_msg, W_ih);

    // 1) embed
    embed_kernel<<<M_PAD / 32, 128, embed_smem>>>(x, W_emb);

    // 2) message-passing steps: gather+GEMM(gx), then GEMM(gh)+fused GRU
    for (int s = 0; s < STEPS; s++) {
        gemm_fused<0><<<M_TILES, 512, GEMM_SMEM>>>(
            wcomb_h + (size_t)s * 3 * H * H, wcomb_l + (size_t)s * 3 * H * H, b_ih);
        gemm_fused<1><<<M_TILES, 512, GEMM_SMEM>>>(whh_h, whh_l, b_hh);
    }

    // 3) pooling
    cudaMemsetAsync(pool_p, 0, N_GRAPHS * H * sizeof(float));
    cudaMemsetAsync(cnt_p, 0, N_GRAPHS * sizeof(float));
    pool_kernel<<<(N_NODES + 255) / 256, 128>>>(batch);

    // 4) head
    head_kernel<<<N_GRAPHS, H>>>(W1, b1, W2, b2, out);
}

// round 7
// speedup vs baseline: 1.6867x; 1.6867x over previous
#include <cuda_runtime.h>
#include <cuda_bf16.h>
#include <math.h>
#include <stdint.h>

#define N_NODES  50000
#define N_EDGES  800000
#define FEAT     90
#define H        128
#define STEPS    4
#define N_GRAPHS 100
#define M_PAD    50048   // 128 * 391
#define M_TILES  (M_PAD / 128)
#define NOUT     384

typedef unsigned long long u64;

// ---------------- device scratch ----------------
__device__ float g_h  [(size_t)M_PAD * H];
__device__ float g_agg[(size_t)M_PAD * H];
__device__ float g_gx [(size_t)M_PAD * 3 * H];
__device__ float g_gh [(size_t)M_PAD * 3 * H];
__device__ float g_pool[N_GRAPHS * H];
__device__ float g_cnt [N_GRAPHS];

// CSR for gather aggregation
__device__ int g_deg[N_NODES];
__device__ int g_off[N_NODES + 1];
__device__ int g_cur[N_NODES];
__device__ int g_eid[N_EDGES];

// bf16-split, transposed weights, layout [n][k]
__device__ __nv_bfloat16 g_wcomb_h[STEPS * 3 * H * H];  // W_msg[s] @ W_ih
__device__ __nv_bfloat16 g_wcomb_l[STEPS * 3 * H * H];
__device__ __nv_bfloat16 g_whh_h[3 * H * H];
__device__ __nv_bfloat16 g_whh_l[3 * H * H];

// ---------------- PTX helpers ----------------
__device__ __forceinline__ uint32_t smem_u32(const void* p) {
    uint32_t a;
    asm("{ .reg .u64 t; cvta.to.shared.u64 t, %1; cvt.u32.u64 %0, t; }" : "=r"(a) : "l"(p));
    return a;
}

__device__ __forceinline__ void ldsm_x4(uint32_t& r0, uint32_t& r1, uint32_t& r2, uint32_t& r3,
                                        uint32_t addr) {
    asm volatile("ldmatrix.sync.aligned.m8n8.x4.shared.b16 {%0,%1,%2,%3}, [%4];"
                 : "=r"(r0), "=r"(r1), "=r"(r2), "=r"(r3) : "r"(addr));
}

__device__ __forceinline__ void mma_bf16(float* c, const uint32_t* a, const uint32_t* b) {
    asm volatile(
        "mma.sync.aligned.m16n8k16.row.col.f32.bf16.bf16.f32 "
        "{%0,%1,%2,%3}, {%4,%5,%6,%7}, {%8,%9}, {%0,%1,%2,%3};"
        : "+f"(c[0]), "+f"(c[1]), "+f"(c[2]), "+f"(c[3])
        : "r"(a[0]), "r"(a[1]), "r"(a[2]), "r"(a[3]), "r"(b[0]), "r"(b[1]));
}

// swizzled tile offset: row r (0..127), 16B-chunk c (0..15); 256B rows
__device__ __forceinline__ uint32_t swz(int r, int c) {
    return (uint32_t)r * 256 + (uint32_t)((c ^ (r & 7)) << 4);
}

__device__ __forceinline__ float sigmoidf_(float x) { return 1.f / (1.f + expf(-x)); }

// ---------------- CSR build ----------------
__global__ void hist_kernel(const int* __restrict__ ei) {
    int e = blockIdx.x * 256 + threadIdx.x;
    if (e < N_EDGES) atomicAdd(&g_deg[ei[N_EDGES + e]], 1);
}

__global__ void scan_kernel() {   // single block, 1024 threads
    const int tid = threadIdx.x, lane = tid & 31, w = tid >> 5;
    __shared__ int wsum[32];
    int total = 0;
    for (int base = 0; base < N_NODES; base += 1024) {
        int i = base + tid;
        int v = (i < N_NODES) ? g_deg[i] : 0;
        int x = v;
        #pragma unroll
        for (int d = 1; d < 32; d <<= 1) {
            int t = __shfl_up_sync(0xFFFFFFFFu, x, d);
            if (lane >= d) x += t;
        }
        if (lane == 31) wsum[w] = x;
        __syncthreads();
        if (w == 0) {
            int y = wsum[lane];
            #pragma unroll
            for (int d = 1; d < 32; d <<= 1) {
                int t = __shfl_up_sync(0xFFFFFFFFu, y, d);
                if (lane >= d) y += t;
            }
            wsum[lane] = y;
        }
        __syncthreads();
        int woff = (w == 0) ? 0 : wsum[w - 1];
        int excl = total + woff + x - v;
        if (i < N_NODES) { g_off[i] = excl; g_cur[i] = excl; }
        int chunk = wsum[31];
        __syncthreads();
        total += chunk;
    }
    if (tid == 0) g_off[N_NODES] = total;
}

__global__ void fill_kernel(const int* __restrict__ ei) {
    int e = blockIdx.x * 256 + threadIdx.x;
    if (e < N_EDGES) {
        int dst = ei[N_EDGES + e];
        int pos = atomicAdd(&g_cur[dst], 1);
        g_eid[pos] = ei[e];
    }
}

// ---------------- gather: agg[n] = sum_{e: dst=n} h[src[e]] ----------------
__global__ void gather_kernel() {
    const int node = (blockIdx.x * blockDim.x + threadIdx.x) >> 5;
    if (node >= N_NODES) return;
    const int lane = threadIdx.x & 31;
    const int beg = g_off[node], end = g_off[node + 1];
    float4 acc = make_float4(0.f, 0.f, 0.f, 0.f);
    #pragma unroll 4
    for (int e = beg; e < end; e++) {
        int src = __ldg(&g_eid[e]);
        float4 v = *(const float4*)(g_h + (size_t)src * H + lane * 4);
        acc.x += v.x; acc.y += v.y; acc.z += v.z; acc.w += v.w;
    }
    *(float4*)(g_agg + (size_t)node * H + lane * 4) = acc;
}

// ---------------- weight prep ----------------
__global__ void prep_whh(const float* __restrict__ Whh) {
    int j = blockIdx.x * 256 + threadIdx.x;
    if (j >= 3 * H * H) return;
    int n = j >> 7, k = j & 127;
    float v = Whh[k * 384 + n];
    __nv_bfloat16 hi = __float2bfloat16(v);
    __nv_bfloat16 lo = __float2bfloat16(v - __bfloat162float(hi));
    g_whh_h[j] = hi; g_whh_l[j] = lo;
}

__global__ void prep_wcomb(const float* __restrict__ Wmsg,
                           const float* __restrict__ Wih) {
    int i = blockIdx.x * 256 + threadIdx.x;
    if (i >= STEPS * 3 * H * H) return;
    int s = i / (3 * H * H);
    int r = i % (3 * H * H);
    int k = r / 384;
    int n = r % 384;
    const float* wm = Wmsg + (s << 14) + k * H;
    float acc = 0.f;
    #pragma unroll 8
    for (int j = 0; j < H; j++) acc = fmaf(wm[j], Wih[j * 384 + n], acc);
    __nv_bfloat16 hi = __float2bfloat16(acc);
    __nv_bfloat16 lo = __float2bfloat16(acc - __bfloat162float(hi));
    size_t o = (size_t)s * 3 * H * H + (size_t)n * H + k;
    g_wcomb_h[o] = hi; g_wcomb_l[o] = lo;
}

// ---------------- mma.sync GEMM: C[M_PAD,384] = A[M_PAD,128] @ W[128,384] + b --
// bf16x3: C = Ah*Bh + Ah*Bl + Al*Bh (fp32 accum). 512 thr, warp tile m32 x n32.
#define SM_A_H 0
#define SM_A_L 32768
#define SM_B_H 65536
#define SM_B_L 98304
#define SM_BIAS 131072
#define GEMM_SMEM (131072 + 1536)

__global__ void __launch_bounds__(512, 1) gemm_mma(
        const float* __restrict__ A,
        const __nv_bfloat16* __restrict__ Bh, const __nv_bfloat16* __restrict__ Bl,
        const float* __restrict__ bias, float* __restrict__ C) {
    extern __shared__ char smem[];
    const uint32_t sbase = smem_u32(smem);
    const int tid = threadIdx.x;
    const int wid = tid >> 5;
    const int lane = tid & 31;
    const int m0 = blockIdx.x * 128;

    // ---- load A tile (128x128 fp32), split to bf16 hi/lo, swizzled store ----
    {
        const float* Ab = A + (size_t)m0 * 128;
        #pragma unroll
        for (int it = 0; it < 8; it++) {
            int idx = it * 512 + tid;          // 0..4095
            int row = idx >> 5;
            int q = idx & 31;                  // float4 index; k0 = q*4
            float4 v = *(const float4*)(Ab + row * 128 + q * 4);
            __nv_bfloat16 h0 = __float2bfloat16(v.x);
            __nv_bfloat16 h1 = __float2bfloat16(v.y);
            __nv_bfloat16 h2 = __float2bfloat16(v.z);
            __nv_bfloat16 h3 = __float2bfloat16(v.w);
            __nv_bfloat16 l0 = __float2bfloat16(v.x - __bfloat162float(h0));
            __nv_bfloat16 l1 = __float2bfloat16(v.y - __bfloat162float(h1));
            __nv_bfloat16 l2 = __float2bfloat16(v.z - __bfloat162float(h2));
            __nv_bfloat16 l3 = __float2bfloat16(v.w - __bfloat162float(h3));
            uint32_t off = swz(row, q >> 1) + (q & 1) * 8;
            uint2 hw, lw;
            hw.x = (uint32_t)__bfloat16_as_ushort(h0) | ((uint32_t)__bfloat16_as_ushort(h1) << 16);
            hw.y = (uint32_t)__bfloat16_as_ushort(h2) | ((uint32_t)__bfloat16_as_ushort(h3) << 16);
            lw.x = (uint32_t)__bfloat16_as_ushort(l0) | ((uint32_t)__bfloat16_as_ushort(l1) << 16);
            lw.y = (uint32_t)__bfloat16_as_ushort(l2) | ((uint32_t)__bfloat16_as_ushort(l3) << 16);
            *(uint2*)(smem + SM_A_H + off) = hw;
            *(uint2*)(smem + SM_A_L + off) = lw;
        }
    }
    // ---- bias -> smem ----
    for (int i = tid; i < NOUT; i += 512)
        *(float*)(smem + SM_BIAS + i * 4) = bias[i];

    const int wm = (wid & 3) * 32;          // warp row offset
    const int wn = (wid >> 2) * 32;         // warp col offset within tile

    #pragma unroll
    for (int nt = 0; nt < 3; nt++) {
        __syncthreads();
        // ---- load B sub-tile 128n x 128k hi+lo, swizzled ----
        {
            const __nv_bfloat16* bh = Bh + (size_t)nt * 128 * 128;
            const __nv_bfloat16* bl = Bl + (size_t)nt * 128 * 128;
            #pragma unroll
            for (int it = 0; it < 4; it++) {
                int idx = it * 512 + tid;       // 0..2047
                int row = idx >> 4;
                int c = idx & 15;
                uint32_t off = swz(row, c);
                *(uint4*)(smem + SM_B_H + off) = *(const uint4*)(bh + row * 128 + c * 8);
                *(uint4*)(smem + SM_B_L + off) = *(const uint4*)(bl + row * 128 + c * 8);
            }
        }
        __syncthreads();

        // ---- compute: 8 k-steps, warp tile m32 x n32 ----
        float acc[2][4][4];
        #pragma unroll
        for (int mi = 0; mi < 2; mi++)
            #pragma unroll
            for (int ni = 0; ni < 4; ni++)
                #pragma unroll
                for (int j = 0; j < 4; j++) acc[mi][ni][j] = 0.f;

        #pragma unroll
        for (int ks = 0; ks < 8; ks++) {
            const int c0 = ks * 2;
            uint32_t ah[2][4], al[2][4], bh[4][2], bl[4][2];
            {
                int arow = (lane & 15);
                int ac = c0 + (lane >> 4);
                #pragma unroll
                for (int mi = 0; mi < 2; mi++) {
                    uint32_t o = swz(wm + mi * 16 + arow, ac);
                    ldsm_x4(ah[mi][0], ah[mi][1], ah[mi][2], ah[mi][3], sbase + SM_A_H + o);
                    ldsm_x4(al[mi][0], al[mi][1], al[mi][2], al[mi][3], sbase + SM_A_L + o);
                }
            }
            {
                int brow = ((lane >> 4) << 3) + (lane & 7);
                int bc = c0 + ((lane >> 3) & 1);
                #pragma unroll
                for (int nj = 0; nj < 2; nj++) {
                    uint32_t o = swz(wn + nj * 16 + brow, bc);
                    uint32_t t0, t1, t2, t3;
                    ldsm_x4(t0, t1, t2, t3, sbase + SM_B_H + o);
                    bh[nj * 2][0] = t0; bh[nj * 2][1] = t1;
                    bh[nj * 2 + 1][0] = t2; bh[nj * 2 + 1][1] = t3;
                    ldsm_x4(t0, t1, t2, t3, sbase + SM_B_L + o);
                    bl[nj * 2][0] = t0; bl[nj * 2][1] = t1;
                    bl[nj * 2 + 1][0] = t2; bl[nj * 2 + 1][1] = t3;
                }
            }
            #pragma unroll
            for (int mi = 0; mi < 2; mi++)
                #pragma unroll
                for (int ni = 0; ni < 4; ni++) {
                    mma_bf16(acc[mi][ni], ah[mi], bh[ni]);
                    mma_bf16(acc[mi][ni], ah[mi], bl[ni]);
                    mma_bf16(acc[mi][ni], al[mi], bh[ni]);
                }
        }

        // ---- epilogue ----
        {
            const int r0 = m0 + wm + (lane >> 2);
            const int cb = nt * 128 + wn + (lane & 3) * 2;
            #pragma unroll
            for (int mi = 0; mi < 2; mi++) {
                #pragma unroll
                for (int ni = 0; ni < 4; ni++) {
                    int col = cb + ni * 8;
                    float2 bb = *(const float2*)(smem + SM_BIAS + col * 4);
                    float* c0p = C + (size_t)(r0 + mi * 16) * NOUT + col;
                    float* c1p = C + (size_t)(r0 + mi * 16 + 8) * NOUT + col;
                    *(float2*)c0p = make_float2(acc[mi][ni][0] + bb.x, acc[mi][ni][1] + bb.y);
                    *(float2*)c1p = make_float2(acc[mi][ni][2] + bb.x, acc[mi][ni][3] + bb.y);
                }
            }
        }
    }
}

// ---------------- embedding: h = relu(x @ W_emb), K=90 ----------------
__global__ void embed_kernel(const float* __restrict__ x,
                             const float* __restrict__ Wemb) {
    extern __shared__ float sm[];
    float* Ws = sm;               // FEAT*H
    float* xs = sm + FEAT * H;    // 32*FEAT
    const int tid = threadIdx.x;
    for (int i = tid; i < FEAT * H; i += 128) Ws[i] = Wemb[i];
    const int n0 = blockIdx.x * 32;
    for (int i = tid; i < 32 * FEAT; i += 128) {
        int r = i / FEAT, cc = i - r * FEAT;
        int n = n0 + r;
        xs[i] = (n < N_NODES) ? x[(size_t)n * FEAT + cc] : 0.f;
    }
    __syncthreads();
    const int c = tid;
    for (int r = 0; r < 32; r++) {
        float acc = 0.f;
        const float* xr = xs + r * FEAT;
        #pragma unroll 6
        for (int k = 0; k < FEAT; k++) acc = fmaf(xr[k], Ws[k * H + c], acc);
        g_h[(size_t)(n0 + r) * H + c] = fmaxf(acc, 0.f);
    }
}

// ---------------- GRU elementwise (float4 vectorized) ------------------------
__global__ void gru_kernel() {
    const int v = blockIdx.x * blockDim.x + threadIdx.x;  // vec4 index, < M_PAD*32
    const int node = v >> 5;
    const int c4 = (v & 31) * 4;
    const size_t gb = (size_t)node * 384 + c4;
    const size_t hb = (size_t)node * 128 + c4;
    float4 xr = *(const float4*)&g_gx[gb];
    float4 xz = *(const float4*)&g_gx[gb + 128];
    float4 xn = *(const float4*)&g_gx[gb + 256];
    float4 hr = *(const float4*)&g_gh[gb];
    float4 hz = *(const float4*)&g_gh[gb + 128];
    float4 hn = *(const float4*)&g_gh[gb + 256];
    float4 hv = *(const float4*)&g_h[hb];
    float4 o;
    {
        float r = sigmoidf_(xr.x + hr.x), z = sigmoidf_(xz.x + hz.x);
        float nn = tanhf(xn.x + r * hn.x);
        o.x = (1.f - z) * nn + z * hv.x;
    }
    {
        float r = sigmoidf_(xr.y + hr.y), z = sigmoidf_(xz.y + hz.y);
        float nn = tanhf(xn.y + r * hn.y);
        o.y = (1.f - z) * nn + z * hv.y;
    }
    {
        float r = sigmoidf_(xr.z + hr.z), z = sigmoidf_(xz.z + hz.z);
        float nn = tanhf(xn.z + r * hn.z);
        o.z = (1.f - z) * nn + z * hv.z;
    }
    {
        float r = sigmoidf_(xr.w + hr.w), z = sigmoidf_(xz.w + hz.w);
        float nn = tanhf(xn.w + r * hn.w);
        o.w = (1.f - z) * nn + z * hv.w;
    }
    *(float4*)&g_h[hb] = o;
}

// ---------------- pooling: sum relu(h) per graph (batch sorted) --------------
__global__ void pool_kernel(const int* __restrict__ batch) {
    __shared__ int bs[256];
    const int tid = threadIdx.x;        // 128 threads, one column each
    const int n0 = blockIdx.x * 256;
    const int cnt = min(256, N_NODES - n0);
    for (int i = tid; i < cnt; i += 128) bs[i] = batch[n0 + i];
    __syncthreads();
    const int c = tid;
    float sum = 0.f;
    int cur = bs[0];
    int run = 0;
    for (int i = 0; i < cnt; i++) {
        int b = bs[i];
        if (b != cur) {
            atomicAdd(&g_pool[cur * H + c], sum);
            if (c == 0) atomicAdd(&g_cnt[cur], (float)run);
            sum = 0.f; run = 0; cur = b;
        }
        sum += fmaxf(g_h[(size_t)(n0 + i) * H + c], 0.f);
        run++;
    }
    atomicAdd(&g_pool[cur * H + c], sum);
    if (c == 0) atomicAdd(&g_cnt[cur], (float)run);
}

// ---------------- head: mean -> Linear+ReLU -> Linear -> softplus ------------
__global__ void head_kernel(const float* __restrict__ W1, const float* __restrict__ b1,
                            const float* __restrict__ W2, const float* __restrict__ b2,
                            float* __restrict__ out) {
    __shared__ float ps[H];
    __shared__ float hs[H];
    const int g = blockIdx.x, c = threadIdx.x;
    float cnt = fmaxf(g_cnt[g], 1.f);
    ps[c] = g_pool[g * H + c] / cnt;
    __syncthreads();
    float acc = b1[c];
    #pragma unroll 8
    for (int k = 0; k < H; k++) acc = fmaf(ps[k], W1[k * H + c], acc);
    hs[c] = fmaxf(acc, 0.f) * W2[c];
    __syncthreads();
    for (int s = 64; s > 0; s >>= 1) {
        if (c < s) hs[c] += hs[c + s];
        __syncthreads();
    }
    if (c == 0) {
        float xv = hs[0] + b2[0];
        out[g] = (xv > 0.f) ? (xv + log1pf(expf(-xv))) : log1pf(expf(xv));
    }
}

// ---------------- launch ------------------------------------------------------
extern "C" void kernel_launch(void* const* d_in, const int* in_sizes, int n_in,
                              void* d_out, int out_size) {
    const float* x     = (const float*)d_in[0];
    const int*   ei    = (const int*)d_in[1];
    const int*   batch = (const int*)d_in[2];
    const float* W_emb = (const float*)d_in[3];
    const float* W_msg = (const float*)d_in[4];
    const float* W_ih  = (const float*)d_in[5];
    const float* W_hh  = (const float*)d_in[6];
    const float* b_ih  = (const float*)d_in[7];
    const float* b_hh  = (const float*)d_in[8];
    const float* W1    = (const float*)d_in[9];
    const float* b1    = (const float*)d_in[10];
    const float* W2    = (const float*)d_in[11];
    const float* b2    = (const float*)d_in[12];
    float* out = (float*)d_out;

    float *h_p, *agg_p, *gx_p, *gh_p, *pool_p, *cnt_p;
    int* deg_p;
    cudaGetSymbolAddress((void**)&h_p,   g_h);
    cudaGetSymbolAddress((void**)&agg_p, g_agg);
    cudaGetSymbolAddress((void**)&gx_p,  g_gx);
    cudaGetSymbolAddress((void**)&gh_p,  g_gh);
    cudaGetSymbolAddress((void**)&pool_p, g_pool);
    cudaGetSymbolAddress((void**)&cnt_p,  g_cnt);
    cudaGetSymbolAddress((void**)&deg_p,  g_deg);

    __nv_bfloat16 *wcomb_h, *wcomb_l, *whh_h, *whh_l;
    cudaGetSymbolAddress((void**)&wcomb_h, g_wcomb_h);
    cudaGetSymbolAddress((void**)&wcomb_l, g_wcomb_l);
    cudaGetSymbolAddress((void**)&whh_h,   g_whh_h);
    cudaGetSymbolAddress((void**)&whh_l,   g_whh_l);

    const int embed_smem = (FEAT * H + 32 * FEAT) * 4;  // 57600 B
    cudaFuncSetAttribute(embed_kernel,
                         cudaFuncAttributeMaxDynamicSharedMemorySize, embed_smem);
    cudaFuncSetAttribute(gemm_mma,
                         cudaFuncAttributeMaxDynamicSharedMemorySize, GEMM_SMEM);

    // side stream + events for capture-safe fork/join
    cudaStream_t s2;
    cudaStreamCreateWithFlags(&s2, cudaStreamNonBlocking);
    cudaEvent_t evF, evJ;
    cudaEventCreateWithFlags(&evF, cudaEventDisableTiming);
    cudaEventCreateWithFlags(&evJ, cudaEventDisableTiming);

    // ---- setup phase: CSR build (stream 0)  ||  weight prep + embed (s2) ----
    cudaEventRecord(evF, 0);
    cudaStreamWaitEvent(s2, evF, 0);
    prep_whh<<<(3 * H * H + 255) / 256, 256, 0, s2>>>(W_hh);
    prep_wcomb<<<(STEPS * 3 * H * H + 255) / 256, 256, 0, s2>>>(W_msg, W_ih);
    embed_kernel<<<M_PAD / 32, 128, embed_smem, s2>>>(x, W_emb);
    cudaEventRecord(evJ, s2);

    cudaMemsetAsync(deg_p, 0, N_NODES * sizeof(int));
    hist_kernel<<<(N_EDGES + 255) / 256, 256>>>(ei);
    scan_kernel<<<1, 1024>>>();
    fill_kernel<<<(N_EDGES + 255) / 256, 256>>>(ei);
    cudaStreamWaitEvent(0, evJ, 0);

    // ---- message-passing steps: gh-GEMM (s2) overlaps gather+gx-GEMM (0) ----
    for (int s = 0; s < STEPS; s++) {
        cudaEventRecord(evF, 0);
        cudaStreamWaitEvent(s2, evF, 0);
        gemm_mma<<<M_TILES, 512, GEMM_SMEM, s2>>>(h_p, whh_h, whh_l, b_hh, gh_p);
        cudaEventRecord(evJ, s2);

        gather_kernel<<<(N_NODES * 32) / 256, 256>>>();
        gemm_mma<<<M_TILES, 512, GEMM_SMEM>>>(
            agg_p, wcomb_h + (size_t)s * 3 * H * H, wcomb_l + (size_t)s * 3 * H * H,
            b_ih, gx_p);

        cudaStreamWaitEvent(0, evJ, 0);
        gru_kernel<<<(M_PAD * 32) / 256, 256>>>();
    }

    // ---- pooling + head ----
    cudaMemsetAsync(pool_p, 0, N_GRAPHS * H * sizeof(float));
    cudaMemsetAsync(cnt_p, 0, N_GRAPHS * sizeof(float));
    pool_kernel<<<(N_NODES + 255) / 256, 128>>>(batch);
    head_kernel<<<N_GRAPHS, H>>>(W1, b1, W2, b2, out);

    cudaEventDestroy(evF);
    cudaEventDestroy(evJ);
    cudaStreamDestroy(s2);
}